// round 1
// baseline (speedup 1.0000x reference)
#include <cuda_runtime.h>

// Problem constants
#define BATCH 2048
#define RPOS  60
#define KW    13
#define CIN   64
#define CMID  64
#define COUT  128
#define EPSV  1e-5f

// smem y-tile row stride (floats): 68 = 64 + 4 pad -> multiple of 4 (16B aligned
// float4) and 68 % 32 == 4 so distinct j rows land on different bank quads.
#define YSTR 68

// Scratch (device globals: allocation-free rule)
__device__ float g_y1[BATCH * RPOS * CIN];   // relu(bn1(x)), layout [b][r][c]
__device__ float g_y2[BATCH * RPOS * CMID];  // relu(bn2(conv1)), layout [b][r][c]
__device__ float g_y3[BATCH * RPOS * CIN];   // relu(bn3(x)), layout [b][r][c]

// ---------------------------------------------------------------------------
// prep: y1 = relu(bn1(x)), y3 = relu(bn3(x)); transpose [b][c][r] -> [b][r][c]
// ---------------------------------------------------------------------------
__global__ void prep_kernel(const float* __restrict__ x,
                            const float* __restrict__ g1, const float* __restrict__ b1,
                            const float* __restrict__ m1, const float* __restrict__ v1,
                            const float* __restrict__ g3, const float* __restrict__ b3,
                            const float* __restrict__ m3, const float* __restrict__ v3)
{
    __shared__ float xs[64 * 61];     // [c][j], stride 61 (odd) -> conflict-free
    __shared__ float s1a[64], s1b[64], s3a[64], s3b[64];

    int b = blockIdx.x;
    int t = threadIdx.x;  // 256 threads

    if (t < 64) {
        float i1 = g1[t] * rsqrtf(v1[t] + EPSV);
        s1a[t] = i1; s1b[t] = b1[t] - m1[t] * i1;
        float i3 = g3[t] * rsqrtf(v3[t] + EPSV);
        s3a[t] = i3; s3b[t] = b3[t] - m3[t] * i3;
    }
    const float* xb = x + (size_t)b * (CIN * RPOS);
    for (int i = t; i < CIN * RPOS; i += 256) {
        xs[(i / RPOS) * 61 + (i % RPOS)] = xb[i];
    }
    __syncthreads();

    float* y1b = g_y1 + (size_t)b * (RPOS * CIN);
    float* y3b = g_y3 + (size_t)b * (RPOS * CIN);
    for (int i = t; i < RPOS * CIN; i += 256) {
        int j = i >> 6, c = i & 63;
        float xv = xs[c * 61 + j];
        y1b[i] = fmaxf(fmaf(xv, s1a[c], s1b[c]), 0.0f);
        y3b[i] = fmaxf(fmaf(xv, s3a[c], s3b[c]), 0.0f);
    }
}

// ---------------------------------------------------------------------------
// conv_mid: f1 = conv(gather(y1), W1) + c1 ; y2 = relu(bn2(f1))
// CTA = 2 batches x 60 r x 64 o.  threads (24,16)=384.
// microtile: 4 o x 5 r per thread.
// ---------------------------------------------------------------------------
__global__ __launch_bounds__(384) void conv_mid_kernel(
    const float* __restrict__ W1, const float* __restrict__ c1,
    const int*   __restrict__ nei,
    const float* __restrict__ g2, const float* __restrict__ b2,
    const float* __restrict__ m2, const float* __restrict__ v2)
{
    extern __shared__ float sm[];
    float* ys   = sm;                        // 2 * 60 * 68 = 8160 floats
    float* wk   = sm + 8160;                 // [c][o] 64*64 = 4096 floats
    int*   neis = (int*)(sm + 8160 + 4096);  // 780 ints
    float* sb   = sm + 8160 + 4096 + 780;    // 64: conv bias c1
    float* si   = sb + 64;                   // 64: bn2 inv
    float* sa   = si + 64;                   // 64: bn2 add

    int b0 = blockIdx.x * 2;
    int tx = threadIdx.x, ty = threadIdx.y;
    int t = ty * 24 + tx;

    for (int i = t; i < RPOS * KW; i += 384) neis[i] = nei[i];
    if (t < 64) {
        sb[t] = c1[t];
        float iv = g2[t] * rsqrtf(v2[t] + EPSV);
        si[t] = iv; sa[t] = b2[t] - m2[t] * iv;
    }
    const float* src = g_y1 + (size_t)b0 * (RPOS * CIN);
    for (int i = t; i < 2 * RPOS * CIN; i += 384) {
        int bb = i / (RPOS * CIN), rr = i % (RPOS * CIN);
        int j = rr >> 6, c = rr & 63;
        ys[bb * (RPOS * YSTR) + j * YSTR + c] = src[i];
    }

    int bl = tx / 12;              // batch within CTA
    int r0 = (tx % 12) * 5;        // 5 consecutive r per thread
    int o0 = ty * 4;               // 4 consecutive o per thread

    float acc[4][5];
#pragma unroll
    for (int a = 0; a < 4; a++)
#pragma unroll
        for (int q = 0; q < 5; q++) acc[a][q] = 0.0f;

    for (int k = 0; k < KW; k++) {
        __syncthreads();
        for (int i = t; i < CMID * CIN; i += 384) {
            int o = i >> 6, c = i & 63;
            wk[c * CMID + o] = W1[o * (CIN * KW) + c * KW + k];
        }
        __syncthreads();

        int jb[5];
#pragma unroll
        for (int ni = 0; ni < 5; ni++)
            jb[ni] = bl * (RPOS * YSTR) + neis[(r0 + ni) * KW + k] * YSTR;

#pragma unroll 2
        for (int c4 = 0; c4 < CIN; c4 += 4) {
            float yv[5][4];
#pragma unroll
            for (int ni = 0; ni < 5; ni++) {
                float4 v = *(const float4*)&ys[jb[ni] + c4];
                yv[ni][0] = v.x; yv[ni][1] = v.y; yv[ni][2] = v.z; yv[ni][3] = v.w;
            }
#pragma unroll
            for (int cc = 0; cc < 4; cc++) {
                float4 w = *(const float4*)&wk[(c4 + cc) * CMID + o0];
                float wv[4] = {w.x, w.y, w.z, w.w};
#pragma unroll
                for (int oi = 0; oi < 4; oi++)
#pragma unroll
                    for (int ni = 0; ni < 5; ni++)
                        acc[oi][ni] = fmaf(wv[oi], yv[ni][cc], acc[oi][ni]);
            }
        }
    }

    // epilogue: bn2 + relu, write y2 [b][r][c]
    float* dst = g_y2 + (size_t)(b0 + bl) * (RPOS * CMID);
#pragma unroll
    for (int ni = 0; ni < 5; ni++) {
        int r = r0 + ni;
        float4 o4;
        float* pv = (float*)&o4;
#pragma unroll
        for (int oi = 0; oi < 4; oi++) {
            int o = o0 + oi;
            float f = acc[oi][ni] + sb[o];
            pv[oi] = fmaxf(fmaf(f, si[o], sa[o]), 0.0f);
        }
        *(float4*)&dst[r * CMID + o0] = o4;
    }
}

// ---------------------------------------------------------------------------
// conv_out: out = conv(gather(y2), W2)+c2 + conv(gather(y3), W3)+c3
// CTA = 2 batches x 60 r x 128 o.  threads (24,16)=384.
// microtile: 8 o x 5 r per thread.  Two phases share one ys buffer + acc.
// ---------------------------------------------------------------------------
__global__ __launch_bounds__(384) void conv_out_kernel(
    const float* __restrict__ W2, const float* __restrict__ c2,
    const float* __restrict__ W3, const float* __restrict__ c3,
    const int*   __restrict__ nei,
    float* __restrict__ out)
{
    extern __shared__ float sm[];
    float* ys   = sm;                        // 8160 floats
    float* wk   = sm + 8160;                 // [c][o] 64*128 = 8192 floats
    int*   neis = (int*)(sm + 8160 + 8192);  // 780
    float* sb   = sm + 8160 + 8192 + 780;    // 128: c2+c3

    int b0 = blockIdx.x * 2;
    int tx = threadIdx.x, ty = threadIdx.y;
    int t = ty * 24 + tx;

    for (int i = t; i < RPOS * KW; i += 384) neis[i] = nei[i];
    if (t < COUT) sb[t] = c2[t] + c3[t];

    int bl = tx / 12;
    int r0 = (tx % 12) * 5;
    int o0 = ty * 8;

    float acc[8][5];
#pragma unroll
    for (int a = 0; a < 8; a++)
#pragma unroll
        for (int q = 0; q < 5; q++) acc[a][q] = 0.0f;

    for (int ph = 0; ph < 2; ph++) {
        const float* ysrc = (ph == 0 ? g_y2 : g_y3) + (size_t)b0 * (RPOS * CMID);
        const float* Wp = (ph == 0) ? W2 : W3;

        __syncthreads();  // previous phase done reading ys
        for (int i = t; i < 2 * RPOS * CMID; i += 384) {
            int bb = i / (RPOS * CMID), rr = i % (RPOS * CMID);
            int j = rr >> 6, c = rr & 63;
            ys[bb * (RPOS * YSTR) + j * YSTR + c] = ysrc[i];
        }

        for (int k = 0; k < KW; k++) {
            __syncthreads();
            for (int i = t; i < COUT * CMID; i += 384) {
                int o = i >> 6, c = i & 63;
                wk[c * COUT + o] = Wp[o * (CMID * KW) + c * KW + k];
            }
            __syncthreads();

            int jb[5];
#pragma unroll
            for (int ni = 0; ni < 5; ni++)
                jb[ni] = bl * (RPOS * YSTR) + neis[(r0 + ni) * KW + k] * YSTR;

#pragma unroll 2
            for (int c4 = 0; c4 < CMID; c4 += 4) {
                float yv[5][4];
#pragma unroll
                for (int ni = 0; ni < 5; ni++) {
                    float4 v = *(const float4*)&ys[jb[ni] + c4];
                    yv[ni][0] = v.x; yv[ni][1] = v.y; yv[ni][2] = v.z; yv[ni][3] = v.w;
                }
#pragma unroll
                for (int cc = 0; cc < 4; cc++) {
                    const float* wrow = &wk[(c4 + cc) * COUT + o0];
                    float4 w0 = *(const float4*)wrow;
                    float4 w1 = *(const float4*)(wrow + 4);
                    float wv[8] = {w0.x, w0.y, w0.z, w0.w, w1.x, w1.y, w1.z, w1.w};
#pragma unroll
                    for (int oi = 0; oi < 8; oi++)
#pragma unroll
                        for (int ni = 0; ni < 5; ni++)
                            acc[oi][ni] = fmaf(wv[oi], yv[ni][cc], acc[oi][ni]);
                }
            }
        }
    }

    // epilogue: + (c2+c3), write out [b][o][r]
    float* dst = out + (size_t)(b0 + bl) * (COUT * RPOS);
#pragma unroll
    for (int oi = 0; oi < 8; oi++) {
        int o = o0 + oi;
        float bias = sb[o];
        float* dp = dst + o * RPOS + r0;
#pragma unroll
        for (int ni = 0; ni < 5; ni++) dp[ni] = acc[oi][ni] + bias;
    }
}

// ---------------------------------------------------------------------------
extern "C" void kernel_launch(void* const* d_in, const int* in_sizes, int n_in,
                              void* d_out, int out_size)
{
    const float* x   = (const float*)d_in[0];
    const int*   nei = (const int*)d_in[1];
    const float* g1 = (const float*)d_in[2];
    const float* b1 = (const float*)d_in[3];
    const float* m1 = (const float*)d_in[4];
    const float* v1 = (const float*)d_in[5];
    const float* W1 = (const float*)d_in[6];
    const float* c1 = (const float*)d_in[7];
    const float* g2 = (const float*)d_in[8];
    const float* b2 = (const float*)d_in[9];
    const float* m2 = (const float*)d_in[10];
    const float* v2 = (const float*)d_in[11];
    const float* W2 = (const float*)d_in[12];
    const float* c2 = (const float*)d_in[13];
    const float* g3 = (const float*)d_in[14];
    const float* b3 = (const float*)d_in[15];
    const float* m3 = (const float*)d_in[16];
    const float* v3 = (const float*)d_in[17];
    const float* W3 = (const float*)d_in[18];
    const float* c3 = (const float*)d_in[19];
    float* out = (float*)d_out;

    const int smem_mid = (8160 + 4096 + 780 + 192) * 4;   // 52912 B
    const int smem_out = (8160 + 8192 + 780 + 128) * 4;   // 69040 B
    cudaFuncSetAttribute(conv_mid_kernel, cudaFuncAttributeMaxDynamicSharedMemorySize, smem_mid);
    cudaFuncSetAttribute(conv_out_kernel, cudaFuncAttributeMaxDynamicSharedMemorySize, smem_out);

    prep_kernel<<<BATCH, 256>>>(x, g1, b1, m1, v1, g3, b3, m3, v3);
    conv_mid_kernel<<<BATCH / 2, dim3(24, 16), smem_mid>>>(W1, c1, nei, g2, b2, m2, v2);
    conv_out_kernel<<<BATCH / 2, dim3(24, 16), smem_out>>>(W2, c2, W3, c3, nei, out);
}

// round 3
// speedup vs baseline: 3.0857x; 3.0857x over previous
#include <cuda_runtime.h>
#include <cuda_bf16.h>
#include <cstdint>

#define BATCH 2048
#define RPOS  60
#define KW    13
#define CIN   64
#define CMID  64
#define COUT  128
#define EPSV  1e-5f

// ---------------------------------------------------------------------------
// Device scratch: y tensors as bf16 hi/lo, layout [b][r][c] (128B rows)
// ---------------------------------------------------------------------------
__device__ __nv_bfloat16 g_y1h[BATCH * RPOS * CIN];
__device__ __nv_bfloat16 g_y1l[BATCH * RPOS * CIN];
__device__ __nv_bfloat16 g_y2h[BATCH * RPOS * CMID];
__device__ __nv_bfloat16 g_y2l[BATCH * RPOS * CMID];
__device__ __nv_bfloat16 g_y3h[BATCH * RPOS * CIN];
__device__ __nv_bfloat16 g_y3l[BATCH * RPOS * CIN];
// Packed weights: [hl][k][o][c] bf16, XOR-swizzle on 16B granules pre-applied
// (granule (c>>3) ^ (o&7)), so stage copies are linear 128B rows.
__device__ __nv_bfloat16 g_W1p[2 * KW * CMID * CIN];
__device__ __nv_bfloat16 g_W2p[2 * KW * COUT * CMID];
__device__ __nv_bfloat16 g_W3p[2 * KW * COUT * CMID];

// ---------------------------------------------------------------------------
// PTX helpers (baseline features only: cp.async, ldmatrix, mma.sync)
// ---------------------------------------------------------------------------
__device__ __forceinline__ uint32_t smem_u32(const void* p) {
    uint32_t a;
    asm("{ .reg .u64 t; cvta.to.shared.u64 t, %1; cvt.u32.u64 %0, t; }" : "=r"(a) : "l"(p));
    return a;
}

#define CP_ASYNC16(dst, src) \
    asm volatile("cp.async.cg.shared.global [%0], [%1], 16;" :: "r"(dst), "l"(src) : "memory")
#define CP_COMMIT()  asm volatile("cp.async.commit_group;" ::: "memory")
#define CP_WAIT(n)   asm volatile("cp.async.wait_group %0;" :: "n"(n) : "memory")

#define LDMX4(r0, r1, r2, r3, addr) \
    asm volatile("ldmatrix.sync.aligned.m8n8.x4.shared.b16 {%0,%1,%2,%3}, [%4];" \
        : "=r"(r0), "=r"(r1), "=r"(r2), "=r"(r3) : "r"(addr))

__device__ __forceinline__ void mma16816(float* d, const uint32_t* a, const uint32_t* b) {
    asm volatile("mma.sync.aligned.m16n8k16.row.col.f32.bf16.bf16.f32 "
        "{%0,%1,%2,%3},{%4,%5,%6,%7},{%8,%9},{%0,%1,%2,%3};"
        : "+f"(d[0]), "+f"(d[1]), "+f"(d[2]), "+f"(d[3])
        : "r"(a[0]), "r"(a[1]), "r"(a[2]), "r"(a[3]), "r"(b[0]), "r"(b[1]));
}

__device__ __forceinline__ void split2(float a, float b, uint32_t& h, uint32_t& l) {
    __nv_bfloat16 ha = __float2bfloat16(a), hb = __float2bfloat16(b);
    __nv_bfloat16 la = __float2bfloat16(a - __bfloat162float(ha));
    __nv_bfloat16 lb = __float2bfloat16(b - __bfloat162float(hb));
    h = (uint32_t)__bfloat16_as_ushort(ha) | ((uint32_t)__bfloat16_as_ushort(hb) << 16);
    l = (uint32_t)__bfloat16_as_ushort(la) | ((uint32_t)__bfloat16_as_ushort(lb) << 16);
}

__device__ __forceinline__ void copy_row8(uint32_t dst, const char* src, int sw) {
#pragma unroll
    for (int g = 0; g < 8; g++) CP_ASYNC16(dst + (uint32_t)((g << 4) ^ sw), src + (g << 4));
}

// ---------------------------------------------------------------------------
// prep: y1 = relu(bn1(x)), y3 = relu(bn3(x)); [b][c][r] -> [b][r][c] bf16 hi/lo
// ---------------------------------------------------------------------------
__global__ void prep_kernel(const float* __restrict__ x,
                            const float* __restrict__ g1, const float* __restrict__ b1,
                            const float* __restrict__ m1, const float* __restrict__ v1,
                            const float* __restrict__ g3, const float* __restrict__ b3,
                            const float* __restrict__ m3, const float* __restrict__ v3)
{
    __shared__ float xs[64 * 61];
    __shared__ float s1a[64], s1b[64], s3a[64], s3b[64];
    int b = blockIdx.x, t = threadIdx.x;

    if (t < 64) {
        float i1 = g1[t] * rsqrtf(v1[t] + EPSV);
        s1a[t] = i1; s1b[t] = b1[t] - m1[t] * i1;
        float i3 = g3[t] * rsqrtf(v3[t] + EPSV);
        s3a[t] = i3; s3b[t] = b3[t] - m3[t] * i3;
    }
    const float* xb = x + (size_t)b * (CIN * RPOS);
    for (int i = t; i < CIN * RPOS; i += 256)
        xs[(i / RPOS) * 61 + (i % RPOS)] = xb[i];
    __syncthreads();

    uint32_t* y1h = (uint32_t*)g_y1h + (size_t)b * (RPOS * 32);
    uint32_t* y1l = (uint32_t*)g_y1l + (size_t)b * (RPOS * 32);
    uint32_t* y3h = (uint32_t*)g_y3h + (size_t)b * (RPOS * 32);
    uint32_t* y3l = (uint32_t*)g_y3l + (size_t)b * (RPOS * 32);
    for (int i = t; i < RPOS * 32; i += 256) {
        int j = i >> 5, c = (i & 31) * 2;
        float xa = xs[c * 61 + j], xc = xs[(c + 1) * 61 + j];
        float a1 = fmaxf(fmaf(xa, s1a[c], s1b[c]), 0.0f);
        float b1v = fmaxf(fmaf(xc, s1a[c + 1], s1b[c + 1]), 0.0f);
        float a3 = fmaxf(fmaf(xa, s3a[c], s3b[c]), 0.0f);
        float b3v = fmaxf(fmaf(xc, s3a[c + 1], s3b[c + 1]), 0.0f);
        uint32_t h, l;
        split2(a1, b1v, h, l); y1h[i] = h; y1l[i] = l;
        split2(a3, b3v, h, l); y3h[i] = h; y3l[i] = l;
    }
}

// ---------------------------------------------------------------------------
// packW: [o][c][k] fp32 -> [hl][k][o][c-swizzled] bf16
// ---------------------------------------------------------------------------
__global__ void packW_kernel(const float* __restrict__ W1, const float* __restrict__ W2,
                             const float* __restrict__ W3)
{
    int idx = blockIdx.x * 256 + threadIdx.x;
    const int n1 = KW * CMID * CIN, n2 = KW * COUT * CMID;
    const float* W; __nv_bfloat16* dst; int O, nloc;
    if (idx < n1)             { W = W1; dst = g_W1p; O = CMID; nloc = idx;           }
    else if (idx < n1 + n2)   { W = W2; dst = g_W2p; O = COUT; nloc = idx - n1;      }
    else if (idx < n1 + 2*n2) { W = W3; dst = g_W3p; O = COUT; nloc = idx - n1 - n2; }
    else return;
    int k = nloc / (O * 64), rem = nloc % (O * 64);
    int o = rem / 64, c = rem % 64;
    float v = W[o * (64 * KW) + c * KW + k];
    __nv_bfloat16 h = __float2bfloat16(v);
    __nv_bfloat16 l = __float2bfloat16(v - __bfloat162float(h));
    int sw = ((c >> 3) ^ (o & 7)) * 8 + (c & 7);
    int n = KW * O * 64;
    dst[(size_t)(k * O + o) * 64 + sw] = h;
    dst[(size_t)n + (size_t)(k * O + o) * 64 + sw] = l;
}

// ---------------------------------------------------------------------------
// conv_mid: y2 = relu(bn2(conv(gather(y1), W1) + c1)), bf16 hi/lo out
// CTA: 2 batches -> M=128 rows (120 real), N=64, 13 k-stages of K=64.
// 8 warps: 4(m) x 2(n), warp tile 32x32.
// smem: 2 slots x (A 32K + W 16K) + nei + bias
// ---------------------------------------------------------------------------
#define MID_SLOT 49152u
#define MID_NEI  98304u
#define MID_BIAS (98304u + 3136u)

__global__ __launch_bounds__(256, 1)
void conv_mid_kernel(const int* __restrict__ nei, const float* __restrict__ c1,
                     const float* __restrict__ g2, const float* __restrict__ b2,
                     const float* __restrict__ m2, const float* __restrict__ v2)
{
    extern __shared__ __align__(1024) char smb[];
    uint32_t sbase = smem_u32(smb);

    int t = threadIdx.x, wid = t >> 5, l = t & 31;
    int*   snei  = (int*)(smb + MID_NEI);
    float* sbias = (float*)(smb + MID_BIAS);

    for (int i = t; i < RPOS * KW; i += 256) snei[i] = nei[i];
    if (t < 64) {
        sbias[t] = c1[t];
        float iv = g2[t] * rsqrtf(v2[t] + EPSV);
        sbias[64 + t] = iv; sbias[128 + t] = b2[t] - m2[t] * iv;
    }
    __syncthreads();

    int b0 = blockIdx.x * 2;
    int hlA = t >> 7, rowA = t & 127;
    int bbA = (rowA >= 60 && rowA < 120) ? 1 : 0;
    int rA  = rowA - bbA * 60 - (rowA >= 120 ? 120 : 0);
    const char* ybase = (const char*)(hlA ? g_y1l : g_y1h)
                      + (((size_t)(b0 + bbA) * RPOS) << 7);
    int swA = (rowA & 7) << 4;

    // copy stage 0
    {
        int j = snei[rA * KW + 0];
        copy_row8(sbase + (uint32_t)((hlA << 7) + rowA) * 128, ybase + ((size_t)j << 7), swA);
        if (t < 128) {
            int hl = t >> 6, o = t & 63;
            const char* ws = (const char*)g_W1p + ((size_t)(hl * KW * CMID + o) << 7);
            copy_row8(sbase + 32768u + (uint32_t)((hl << 6) + o) * 128, ws, 0);
        }
        CP_COMMIT();
    }

    int m0 = (wid & 3) * 32, n0 = (wid >> 2) * 32;
    int lrA = l & 15, lgA = l >> 4;
    int lrB = (l & 7) + ((l >> 4) << 3), lgB = (l >> 3) & 1;

    float acc[2][4][4];
#pragma unroll
    for (int a = 0; a < 2; a++)
#pragma unroll
        for (int b = 0; b < 4; b++)
#pragma unroll
            for (int c = 0; c < 4; c++) acc[a][b][c] = 0.0f;

    for (int s = 0; s < KW; s++) {
        if (s + 1 < KW) {
            uint32_t slot = sbase + (uint32_t)((s + 1) & 1) * MID_SLOT;
            int j = snei[rA * KW + s + 1];
            copy_row8(slot + (uint32_t)((hlA << 7) + rowA) * 128, ybase + ((size_t)j << 7), swA);
            if (t < 128) {
                int hl = t >> 6, o = t & 63;
                const char* ws = (const char*)g_W1p
                               + ((size_t)(hl * KW * CMID + (s + 1) * CMID + o) << 7);
                copy_row8(slot + 32768u + (uint32_t)((hl << 6) + o) * 128, ws, 0);
            }
            CP_COMMIT();
            CP_WAIT(1);
        } else {
            CP_WAIT(0);
        }
        __syncthreads();

        uint32_t Ab = sbase + (uint32_t)(s & 1) * MID_SLOT;
        uint32_t Wb = Ab + 32768u;
#pragma unroll
        for (int ks = 0; ks < 4; ks++) {
            uint32_t ah[2][4], al[2][4], bh[2][4], bl[2][4];
#pragma unroll
            for (int mt = 0; mt < 2; mt++) {
                int row = m0 + mt * 16 + lrA;
                uint32_t ad = Ab + (uint32_t)row * 128
                            + (uint32_t)((((ks << 1) + lgA) ^ (row & 7)) << 4);
                LDMX4(ah[mt][0], ah[mt][1], ah[mt][2], ah[mt][3], ad);
                LDMX4(al[mt][0], al[mt][1], al[mt][2], al[mt][3], ad + 16384u);
            }
#pragma unroll
            for (int q = 0; q < 2; q++) {
                int row = n0 + q * 16 + lrB;
                uint32_t bd = Wb + (uint32_t)row * 128
                            + (uint32_t)((((ks << 1) + lgB) ^ (row & 7)) << 4);
                LDMX4(bh[q][0], bh[q][1], bh[q][2], bh[q][3], bd);
                LDMX4(bl[q][0], bl[q][1], bl[q][2], bl[q][3], bd + 8192u);
            }
#pragma unroll
            for (int mt = 0; mt < 2; mt++)
#pragma unroll
                for (int nt = 0; nt < 4; nt++) {
                    float* d = acc[mt][nt];
                    const uint32_t* B0 = &bh[nt >> 1][(nt & 1) * 2];
                    const uint32_t* B1 = &bl[nt >> 1][(nt & 1) * 2];
                    mma16816(d, ah[mt], B0);
                    mma16816(d, ah[mt], B1);
                    mma16816(d, al[mt], B0);
                }
        }
        __syncthreads();
    }

    // epilogue: bn2+relu, split, store y2
#pragma unroll
    for (int mt = 0; mt < 2; mt++)
#pragma unroll
        for (int nt = 0; nt < 4; nt++) {
            float* d = acc[mt][nt];
            int o = n0 + nt * 8 + ((l & 3) << 1);
            float cv0 = sbias[o],       cv1 = sbias[o + 1];
            float i0  = sbias[64 + o],  i1  = sbias[65 + o];
            float a0  = sbias[128 + o], a1  = sbias[129 + o];
#pragma unroll
            for (int h = 0; h < 2; h++) {
                int m = m0 + mt * 16 + (l >> 2) + h * 8;
                if (m < 120) {
                    int bb = (m >= 60); int r = m - bb * 60;
                    float y0 = fmaxf(fmaf(d[h * 2]     + cv0, i0, a0), 0.0f);
                    float y1 = fmaxf(fmaf(d[h * 2 + 1] + cv1, i1, a1), 0.0f);
                    uint32_t hh, ll; split2(y0, y1, hh, ll);
                    size_t off = (((size_t)(b0 + bb) * RPOS + r) << 5) + (o >> 1);
                    ((uint32_t*)g_y2h)[off] = hh;
                    ((uint32_t*)g_y2l)[off] = ll;
                }
            }
        }
}

// ---------------------------------------------------------------------------
// conv_out: out = conv(gather(y2),W2)+c2 + conv(gather(y3),W3)+c3
// CTA: 2 batches -> M=128 rows, N=128, 26 k-stages.
// 8 warps: 2(m) x 4(n), warp tile 64x32.
// smem: 2 slots x (A 32K + W 32K) + nei + bias; transpose reuses slot memory.
// ---------------------------------------------------------------------------
#define OUT_SLOT 65536u
#define OUT_NEI  131072u
#define OUT_BIAS (131072u + 3136u)

__global__ __launch_bounds__(256, 1)
void conv_out_kernel(const int* __restrict__ nei, const float* __restrict__ c2,
                     const float* __restrict__ c3, float* __restrict__ out)
{
    extern __shared__ __align__(1024) char smb[];
    uint32_t sbase = smem_u32(smb);

    int t = threadIdx.x, wid = t >> 5, l = t & 31;
    int*   snei  = (int*)(smb + OUT_NEI);
    float* sbias = (float*)(smb + OUT_BIAS);

    for (int i = t; i < RPOS * KW; i += 256) snei[i] = nei[i];
    if (t < 128) sbias[t] = c2[t] + c3[t];
    __syncthreads();

    int b0 = blockIdx.x * 2;
    int hlA = t >> 7, rowA = t & 127;
    int bbA = (rowA >= 60 && rowA < 120) ? 1 : 0;
    int rA  = rowA - bbA * 60 - (rowA >= 120 ? 120 : 0);
    int swA = (rowA & 7) << 4;
    size_t ybOff = ((size_t)(b0 + bbA) * RPOS) << 7;

    int oW = t & 127, hlW = t >> 7;

    // copy stage 0 (phase 0: y2 / W2)
    {
        int j = snei[rA * KW + 0];
        const char* ya = (const char*)(hlA ? g_y2l : g_y2h) + ybOff;
        copy_row8(sbase + (uint32_t)((hlA << 7) + rowA) * 128, ya + ((size_t)j << 7), swA);
        const char* ws = (const char*)g_W2p + ((size_t)(hlW * KW * COUT + oW) << 7);
        copy_row8(sbase + 32768u + (uint32_t)((hlW << 7) + oW) * 128, ws, 0);
        CP_COMMIT();
    }

    int m0 = (wid & 1) * 64, n0 = (wid >> 1) * 32;
    int lrA = l & 15, lgA = l >> 4;
    int lrB = (l & 7) + ((l >> 4) << 3), lgB = (l >> 3) & 1;

    float acc[4][4][4];
#pragma unroll
    for (int a = 0; a < 4; a++)
#pragma unroll
        for (int b = 0; b < 4; b++)
#pragma unroll
            for (int c = 0; c < 4; c++) acc[a][b][c] = 0.0f;

    const int S = 2 * KW;
    for (int s = 0; s < S; s++) {
        if (s + 1 < S) {
            int sn = s + 1;
            int ph = sn >= KW, k = sn - ph * KW;
            uint32_t slot = sbase + (uint32_t)(sn & 1) * OUT_SLOT;
            int j = snei[rA * KW + k];
            const char* ya = (const char*)(ph ? (hlA ? g_y3l : g_y3h)
                                              : (hlA ? g_y2l : g_y2h)) + ybOff;
            copy_row8(slot + (uint32_t)((hlA << 7) + rowA) * 128, ya + ((size_t)j << 7), swA);
            const char* ws = (const char*)(ph ? g_W3p : g_W2p)
                           + ((size_t)(hlW * KW * COUT + k * COUT + oW) << 7);
            copy_row8(slot + 32768u + (uint32_t)((hlW << 7) + oW) * 128, ws, 0);
            CP_COMMIT();
            CP_WAIT(1);
        } else {
            CP_WAIT(0);
        }
        __syncthreads();

        uint32_t Ab = sbase + (uint32_t)(s & 1) * OUT_SLOT;
        uint32_t Wb = Ab + 32768u;
#pragma unroll
        for (int ks = 0; ks < 4; ks++) {
            uint32_t ah[4][4], al[4][4], bh[2][4], bl[2][4];
#pragma unroll
            for (int mt = 0; mt < 4; mt++) {
                int row = m0 + mt * 16 + lrA;
                uint32_t ad = Ab + (uint32_t)row * 128
                            + (uint32_t)((((ks << 1) + lgA) ^ (row & 7)) << 4);
                LDMX4(ah[mt][0], ah[mt][1], ah[mt][2], ah[mt][3], ad);
                LDMX4(al[mt][0], al[mt][1], al[mt][2], al[mt][3], ad + 16384u);
            }
#pragma unroll
            for (int q = 0; q < 2; q++) {
                int row = n0 + q * 16 + lrB;
                uint32_t bd = Wb + (uint32_t)row * 128
                            + (uint32_t)((((ks << 1) + lgB) ^ (row & 7)) << 4);
                LDMX4(bh[q][0], bh[q][1], bh[q][2], bh[q][3], bd);
                LDMX4(bl[q][0], bl[q][1], bl[q][2], bl[q][3], bd + 16384u);
            }
#pragma unroll
            for (int mt = 0; mt < 4; mt++)
#pragma unroll
                for (int nt = 0; nt < 4; nt++) {
                    float* d = acc[mt][nt];
                    const uint32_t* B0 = &bh[nt >> 1][(nt & 1) * 2];
                    const uint32_t* B1 = &bl[nt >> 1][(nt & 1) * 2];
                    mma16816(d, ah[mt], B0);
                    mma16816(d, ah[mt], B1);
                    mma16816(d, al[mt], B0);
                }
        }
        __syncthreads();
    }

    // epilogue: +bias, transpose in smem to [o][m] (stride 132), coalesced store
    float* T = (float*)smb;
#pragma unroll
    for (int mt = 0; mt < 4; mt++)
#pragma unroll
        for (int nt = 0; nt < 4; nt++) {
            float* d = acc[mt][nt];
            int o = n0 + nt * 8 + ((l & 3) << 1);
            float bv0 = sbias[o], bv1 = sbias[o + 1];
#pragma unroll
            for (int h = 0; h < 2; h++) {
                int m = m0 + mt * 16 + (l >> 2) + h * 8;
                T[(size_t)o * 132 + m]       = d[h * 2]     + bv0;
                T[(size_t)(o + 1) * 132 + m] = d[h * 2 + 1] + bv1;
            }
        }
    __syncthreads();

    {
        int o = t >> 1, bb = t & 1;
        const float4* src = (const float4*)(T + (size_t)o * 132 + bb * 60);
        float4* dst = (float4*)(out + ((size_t)(b0 + bb) * COUT + o) * RPOS);
#pragma unroll
        for (int q = 0; q < 15; q++) dst[q] = src[q];
    }
}

// ---------------------------------------------------------------------------
extern "C" void kernel_launch(void* const* d_in, const int* in_sizes, int n_in,
                              void* d_out, int out_size)
{
    const float* x   = (const float*)d_in[0];
    const int*   nei = (const int*)d_in[1];
    const float* g1 = (const float*)d_in[2];
    const float* b1 = (const float*)d_in[3];
    const float* m1 = (const float*)d_in[4];
    const float* v1 = (const float*)d_in[5];
    const float* W1 = (const float*)d_in[6];
    const float* c1 = (const float*)d_in[7];
    const float* g2 = (const float*)d_in[8];
    const float* b2 = (const float*)d_in[9];
    const float* m2 = (const float*)d_in[10];
    const float* v2 = (const float*)d_in[11];
    const float* W2 = (const float*)d_in[12];
    const float* c2 = (const float*)d_in[13];
    const float* g3 = (const float*)d_in[14];
    const float* b3 = (const float*)d_in[15];
    const float* m3 = (const float*)d_in[16];
    const float* v3 = (const float*)d_in[17];
    const float* W3 = (const float*)d_in[18];
    const float* c3 = (const float*)d_in[19];
    float* out = (float*)d_out;

    const int smem_mid = (int)(MID_BIAS + 768 + 256);      // ~102.5 KB
    const int smem_out = (int)(OUT_BIAS + 512 + 256);      // ~135 KB
    cudaFuncSetAttribute(conv_mid_kernel, cudaFuncAttributeMaxDynamicSharedMemorySize, smem_mid);
    cudaFuncSetAttribute(conv_out_kernel, cudaFuncAttributeMaxDynamicSharedMemorySize, smem_out);

    prep_kernel<<<BATCH, 256>>>(x, g1, b1, m1, v1, g3, b3, m3, v3);
    packW_kernel<<<(KW * (CMID * CIN + 2 * COUT * CMID) + 255) / 256, 256>>>(W1, W2, W3);
    conv_mid_kernel<<<BATCH / 2, 256, smem_mid>>>(nei, c1, g2, b2, m2, v2);
    conv_out_kernel<<<BATCH / 2, 256, smem_out>>>(nei, c2, c3, out);
}